// round 2
// baseline (speedup 1.0000x reference)
// FSAS_V5 fused forward — one CTA per 8x8 patch, everything in SMEM, fp32.
// Chain: 1x1 expand (384x64) -> depthwise 3x3 -> split q,k,v -> RMSNorm+2D RoPE
//        -> per-patch 8x8 circular conv (== irfft2(rfft2(q)*rfft2(k)))
//        -> RMSNorm -> v*corr -> 1x1 proj (64x128)
#include <cuda_runtime.h>

#define B_   4
#define CI   64
#define CH   384
#define C2   128
#define CO   64
#define HH   256
#define WW   256
#define EPSF 1e-6f

// log2(10000)/32
#define L2T_OVER_32 0.41524101186092030f

// ---- shared memory layout (float offsets) ----
#define OFF_X    0                    // x halo: 64 ch * 100 pos        (25,600 B)
#define OFF_QKV  6400                 // qkv: 384 rows * 65 (padded)    (99,840 B)
#define OFF_U    (6400 + 24960)       // union region: 16,512 floats    (66,048 B)
#define OFF_HID  OFF_U                //   hidden chunk: 96*100 = 9600
#define OFF_W    (OFF_U + 9600)       //   w_hidden chunk: 96*65 = 6240 (padded)
#define OFF_CORR OFF_U                //   corr: 128*65 = 8320
#define OFF_WP   (OFF_U + 8320)       //   w_proj: 64*128 = 8192
#define OFF_WD   (OFF_U + 16512)      // w_dw chunk: 96*9 = 864
#define OFF_RQ   (OFF_WD + 864)       // 64
#define OFF_RK   (OFF_RQ + 64)        // 64
#define OFF_RN   (OFF_RK + 64)        // 64
#define SMEM_FLOATS (OFF_RN + 64)     // 48,928 floats
#define SMEM_BYTES  (SMEM_FLOATS * 4) // 195,712 B

__global__ __launch_bounds__(512, 1)
void fsas_fused_kernel(const float* __restrict__ x,
                       const float* __restrict__ w_hidden,
                       const float* __restrict__ w_dw,
                       const float* __restrict__ w_proj,
                       const float* __restrict__ g_norm,
                       const float* __restrict__ g_qnorm,
                       const float* __restrict__ g_knorm,
                       float* __restrict__ out)
{
    extern __shared__ float sm[];
    const int tid  = threadIdx.x;
    const int lane = tid & 31;
    const int warp = tid >> 5;
    const int px = blockIdx.x, py = blockIdx.y, b = blockIdx.z;
    const int gx0 = px * 8, gy0 = py * 8;

    // ---------------- phase 0: load x halo (10x10, zero-padded) ----------------
    const float* xb = x + (size_t)b * CI * HH * WW;
    for (int idx = tid; idx < CI * 100; idx += 512) {
        int i = idx / 100, pos = idx - i * 100;
        int Y = pos / 10, X = pos - Y * 10;
        int gy = gy0 - 1 + Y, gx = gx0 - 1 + X;
        float v = 0.f;
        if ((unsigned)gy < HH && (unsigned)gx < WW)
            v = __ldg(xb + (size_t)i * (HH * WW) + gy * WW + gx);
        sm[OFF_X + idx] = v;
    }
    __syncthreads();

    // ------- phase 1: expand (1x1, 384x64) + depthwise 3x3, 4 chunks of 96 -------
    for (int chunk = 0; chunk < 4; ++chunk) {
        const int oBase = chunk * 96;
        for (int idx = tid; idx < 96 * 64; idx += 512) {
            int o = idx >> 6, k = idx & 63;
            sm[OFF_W + o * 65 + k] = __ldg(w_hidden + (oBase + o) * 64 + k);
        }
        for (int idx = tid; idx < 96 * 9; idx += 512)
            sm[OFF_WD + idx] = __ldg(w_dw + oBase * 9 + idx);
        __syncthreads();

        // expand: 480 items, each = 4 out-channels x 5 positions
        if (tid < 480) {
            int og = tid / 20, pg = tid - og * 20;
            int o0 = og * 4, p0 = pg * 5;
            float acc[4][5] = {};
            #pragma unroll 4
            for (int k = 0; k < 64; ++k) {
                float xv[5];
                #pragma unroll
                for (int e = 0; e < 5; ++e) xv[e] = sm[OFF_X + k * 100 + p0 + e];
                #pragma unroll
                for (int j = 0; j < 4; ++j) {
                    float wv = sm[OFF_W + (o0 + j) * 65 + k];
                    #pragma unroll
                    for (int e = 0; e < 5; ++e) acc[j][e] = fmaf(wv, xv[e], acc[j][e]);
                }
            }
            #pragma unroll
            for (int j = 0; j < 4; ++j)
                #pragma unroll
                for (int e = 0; e < 5; ++e)
                    sm[OFF_HID + (o0 + j) * 100 + p0 + e] = acc[j][e];
        }
        __syncthreads();

        // depthwise 3x3 on the 10x10 halo -> 8x8 inner, into qkv
        {
            int pix = tid & 63, y = pix >> 3, xq = pix & 7;
            int oL0 = tid >> 6;                  // 0..7
            for (int pass = 0; pass < 12; ++pass) {
                int oL = pass * 8 + oL0;
                const float* wd = &sm[OFF_WD + oL * 9];
                const float* hd = &sm[OFF_HID + oL * 100];
                float s = 0.f;
                #pragma unroll
                for (int dy = 0; dy < 3; ++dy)
                    #pragma unroll
                    for (int dx = 0; dx < 3; ++dx)
                        s = fmaf(wd[dy * 3 + dx], hd[(y + dy) * 10 + xq + dx], s);
                sm[OFF_QKV + (oBase + oL) * 65 + pix] = s;
            }
        }
        __syncthreads();
    }

    // ---------------- phase 2: RMS factors for q and k (per pixel) ----------------
    #pragma unroll
    for (int pi = 0; pi < 4; ++pi) {
        int pix = warp * 4 + pi;
        float sq = 0.f, sk = 0.f;
        #pragma unroll
        for (int r = 0; r < 4; ++r) {
            int c = lane + r * 32;
            float qv = sm[OFF_QKV + c * 65 + pix];
            float kv = sm[OFF_QKV + (128 + c) * 65 + pix];
            sq = fmaf(qv, qv, sq);
            sk = fmaf(kv, kv, sk);
        }
        #pragma unroll
        for (int off = 16; off; off >>= 1) {
            sq += __shfl_xor_sync(0xffffffffu, sq, off);
            sk += __shfl_xor_sync(0xffffffffu, sk, off);
        }
        if (lane == 0) {
            sm[OFF_RQ + pix] = rsqrtf(sq * (1.f / 128.f) + EPSF);
            sm[OFF_RK + pix] = rsqrtf(sk * (1.f / 128.f) + EPSF);
        }
    }
    __syncthreads();

    // ---------------- phase 3: RMSNorm scale + 2D RoPE (q and k share angles) ----
    for (int idx = tid; idx < 64 * 64; idx += 512) {
        int m = idx >> 6, pix = idx & 63;
        int gy = gy0 + (pix >> 3), gx = gx0 + (pix & 7);
        int mm; float pos;
        if (m < 32) { mm = m;      pos = (float)gy; }
        else        { mm = m - 32; pos = (float)gx; }
        float inv = exp2f(-L2T_OVER_32 * (float)mm);
        float sn, cs;
        sincosf(pos * inv, &sn, &cs);
        int c0 = 2 * m;
        float rqp = sm[OFF_RQ + pix], rkp = sm[OFF_RK + pix];

        float q0 = sm[OFF_QKV + c0 * 65 + pix]       * rqp * __ldg(g_qnorm + c0);
        float q1 = sm[OFF_QKV + (c0 + 1) * 65 + pix] * rqp * __ldg(g_qnorm + c0 + 1);
        sm[OFF_QKV + c0 * 65 + pix]       = q0 * cs - q1 * sn;
        sm[OFF_QKV + (c0 + 1) * 65 + pix] = q1 * cs + q0 * sn;

        float k0 = sm[OFF_QKV + (128 + c0) * 65 + pix] * rkp * __ldg(g_knorm + c0);
        float k1 = sm[OFF_QKV + (129 + c0) * 65 + pix] * rkp * __ldg(g_knorm + c0 + 1);
        sm[OFF_QKV + (128 + c0) * 65 + pix] = k0 * cs - k1 * sn;
        sm[OFF_QKV + (129 + c0) * 65 + pix] = k1 * cs + k0 * sn;
    }
    __syncthreads();

    // -------- phase 4: 8x8 circular convolution per channel (direct, unrolled) ----
    // thread -> (channel c, 2 output rows starting at A0). k-tile loaded row-rotated
    // by A0 so every register index below is compile-time (no local-memory spills).
    {
        int c = tid & 127;
        int A0 = (tid >> 7) * 2;          // 0,2,4,6 — uniform per 4-warp group
        float kreg[64];
        #pragma unroll
        for (int n = 0; n < 64; ++n) {
            int rho = n >> 3, col = n & 7;
            int srcRow = (rho + A0) & 7;  // runtime smem index, compile-time reg index
            kreg[n] = sm[OFF_QKV + (128 + c) * 65 + srcRow * 8 + col];
        }
        float acc[2][8] = {};
        #pragma unroll
        for (int i = 0; i < 8; ++i) {
            #pragma unroll
            for (int j = 0; j < 8; ++j) {
                float qv = sm[OFF_QKV + c * 65 + i * 8 + j];
                #pragma unroll
                for (int a2 = 0; a2 < 2; ++a2) {
                    #pragma unroll
                    for (int bb = 0; bb < 8; ++bb)
                        acc[a2][bb] = fmaf(qv, kreg[((a2 - i) & 7) * 8 + ((bb - j) & 7)],
                                           acc[a2][bb]);
                }
            }
        }
        #pragma unroll
        for (int a2 = 0; a2 < 2; ++a2)
            #pragma unroll
            for (int bb = 0; bb < 8; ++bb)
                sm[OFF_CORR + c * 65 + (A0 + a2) * 8 + bb] = acc[a2][bb];
    }
    __syncthreads();

    // ------------- phase 5: load w_proj + corr RMS factor per pixel ---------------
    for (int idx = tid; idx < 64 * 128; idx += 512)
        sm[OFF_WP + idx] = __ldg(w_proj + idx);
    #pragma unroll
    for (int pi = 0; pi < 4; ++pi) {
        int pix = warp * 4 + pi;
        float sc = 0.f;
        #pragma unroll
        for (int r = 0; r < 4; ++r) {
            float cv = sm[OFF_CORR + (lane + r * 32) * 65 + pix];
            sc = fmaf(cv, cv, sc);
        }
        #pragma unroll
        for (int off = 16; off; off >>= 1)
            sc += __shfl_xor_sync(0xffffffffu, sc, off);
        if (lane == 0)
            sm[OFF_RN + pix] = rsqrtf(sc * (1.f / 128.f) + EPSF);
    }
    __syncthreads();

    // ------------- phase 6: corr <- v * g_norm * rn * corr ------------------------
    for (int idx = tid; idx < 128 * 64; idx += 512) {
        int i = idx >> 6, pix = idx & 63;
        float cv = sm[OFF_CORR + i * 65 + pix];
        float vv = sm[OFF_QKV + (256 + i) * 65 + pix];
        sm[OFF_CORR + i * 65 + pix] = vv * cv * sm[OFF_RN + pix] * __ldg(g_norm + i);
    }
    __syncthreads();

    // ------------- phase 7: 1x1 projection (64 x 128) + store ---------------------
    {
        int og = tid >> 5, pg = tid & 31;   // 16 o-groups x 32 pixel-groups
        int o0 = og * 4, p0 = pg * 2;
        float acc[4][2] = {};
        #pragma unroll 4
        for (int kk = 0; kk < 128; ++kk) {
            float v0 = sm[OFF_CORR + kk * 65 + p0];
            float v1 = sm[OFF_CORR + kk * 65 + p0 + 1];
            #pragma unroll
            for (int j = 0; j < 4; ++j) {
                float wv = sm[OFF_WP + (o0 + j) * 128 + kk];
                acc[j][0] = fmaf(wv, v0, acc[j][0]);
                acc[j][1] = fmaf(wv, v1, acc[j][1]);
            }
        }
        float* ob = out + (size_t)b * CO * HH * WW;
        #pragma unroll
        for (int j = 0; j < 4; ++j)
            #pragma unroll
            for (int e = 0; e < 2; ++e) {
                int pix = p0 + e;
                int gy = gy0 + (pix >> 3), gx = gx0 + (pix & 7);
                ob[(size_t)(o0 + j) * (HH * WW) + gy * WW + gx] = acc[j][e];
            }
    }
}

extern "C" void kernel_launch(void* const* d_in, const int* in_sizes, int n_in,
                              void* d_out, int out_size)
{
    (void)in_sizes; (void)n_in; (void)out_size;
    const float* x        = (const float*)d_in[0];
    const float* w_hidden = (const float*)d_in[1];
    const float* w_dw     = (const float*)d_in[2];
    const float* w_proj   = (const float*)d_in[3];
    const float* g_norm   = (const float*)d_in[4];
    const float* g_qnorm  = (const float*)d_in[5];
    const float* g_knorm  = (const float*)d_in[6];
    float* out = (float*)d_out;

    cudaFuncSetAttribute(fsas_fused_kernel,
                         cudaFuncAttributeMaxDynamicSharedMemorySize, SMEM_BYTES);

    dim3 grid(WW / 8, HH / 8, B_);   // (32, 32, 4) = 4096 patches
    fsas_fused_kernel<<<grid, 512, SMEM_BYTES>>>(
        x, w_hidden, w_dw, w_proj, g_norm, g_qnorm, g_knorm, out);
}

// round 4
// speedup vs baseline: 1.6668x; 1.6668x over previous
// FSAS_V5 fused forward — one CTA per 8x8 patch.
// Expand GEMM on mma.sync bf16 (m16n8k16, 2-term hi/lo split => ~fp32 accuracy).
// (tcgen05 unavailable: harness PTX target is compute_103, not sm_103a.)
#include <cuda_runtime.h>
#include <cuda_bf16.h>
#include <cstdint>

#define HH 256
#define WW 256
#define EPSF 1e-6f
#define L2T_OVER_32 0.41524101186092030f

// ---- dynamic smem layout (float offsets) ----
#define OFF_QKV  0                 // 384 * 65 fp32               (99,840 B)
#define OFF_HID  24960             // 128 * 101 fp32 hidden chunk (51,712 B)
#define OFF_CORR OFF_HID           // 128 * 65 overlay (phase 4+)
#define OFF_DW   37888             // 128 * 9 dw weights
#define OFF_RQ   39040
#define OFF_RK   39104
#define OFF_RN   39168
#define ARENA_F  39232             // bf16 tile arena @ byte 156,928 (256-aligned)
// arena byte offsets: rows strided 144 B (72 bf16) -> ldmatrix conflict-free
#define XHI 0                      // Xt hi: 104 pos x 72
#define XLO 14976                  // Xt lo
#define WHI 29952                  // W  hi: 128 o  x 72
#define WLO 48384                  // W  lo
#define ARENA_BYTES 66816
#define SMEM_BYTES (ARENA_F * 4 + ARENA_BYTES)   // 223,744 B

__device__ __forceinline__ uint32_t smem_u32(const void* p) {
    uint32_t a;
    asm("{ .reg .u64 t; cvta.to.shared.u64 t, %1; cvt.u32.u64 %0, t; }"
        : "=r"(a) : "l"(p));
    return a;
}
__device__ __forceinline__ void ldsm4(uint32_t* r, uint32_t addr) {
    asm volatile("ldmatrix.sync.aligned.m8n8.x4.shared.b16 {%0,%1,%2,%3}, [%4];"
                 : "=r"(r[0]), "=r"(r[1]), "=r"(r[2]), "=r"(r[3]) : "r"(addr));
}
__device__ __forceinline__ void ldsm2(uint32_t& r0, uint32_t& r1, uint32_t addr) {
    asm volatile("ldmatrix.sync.aligned.m8n8.x2.shared.b16 {%0,%1}, [%2];"
                 : "=r"(r0), "=r"(r1) : "r"(addr));
}
__device__ __forceinline__ void mma16816(float* c, const uint32_t* a,
                                         uint32_t b0, uint32_t b1) {
    asm volatile("mma.sync.aligned.m16n8k16.row.col.f32.bf16.bf16.f32 "
                 "{%0,%1,%2,%3}, {%4,%5,%6,%7}, {%8,%9}, {%0,%1,%2,%3};"
                 : "+f"(c[0]), "+f"(c[1]), "+f"(c[2]), "+f"(c[3])
                 : "r"(a[0]), "r"(a[1]), "r"(a[2]), "r"(a[3]), "r"(b0), "r"(b1));
}
__device__ __forceinline__ uint32_t pack_hi_lo(float v0, float v1, uint32_t& lo) {
    __nv_bfloat16 h0 = __float2bfloat16(v0);
    __nv_bfloat16 h1 = __float2bfloat16(v1);
    __nv_bfloat16 l0 = __float2bfloat16(v0 - __bfloat162float(h0));
    __nv_bfloat16 l1 = __float2bfloat16(v1 - __bfloat162float(h1));
    lo = ((uint32_t)__bfloat16_as_ushort(l1) << 16) | __bfloat16_as_ushort(l0);
    return ((uint32_t)__bfloat16_as_ushort(h1) << 16) | __bfloat16_as_ushort(h0);
}

__global__ __launch_bounds__(512, 1)
void fsas_fused_kernel(const float* __restrict__ x,
                       const float* __restrict__ w_hidden,
                       const float* __restrict__ w_dw,
                       const float* __restrict__ w_proj,
                       const float* __restrict__ g_norm,
                       const float* __restrict__ g_qnorm,
                       const float* __restrict__ g_knorm,
                       float* __restrict__ out)
{
    extern __shared__ float sm[];
    const int tid  = threadIdx.x;
    const int lane = tid & 31;
    const int warp = tid >> 5;
    const int px = blockIdx.x, py = blockIdx.y, b = blockIdx.z;
    const int gx0 = px * 8, gy0 = py * 8;

    char* smc = (char*)sm;
    const uint32_t sbase = smem_u32(sm);
    const uint32_t arena = sbase + ARENA_F * 4;

    // ---- phase 0: x halo -> bf16 hi/lo Xt tiles, layout [pos(104)][ch(64)+pad] ----
    const float* xb = x + (size_t)b * 64 * HH * WW;
    for (int idx = tid; idx < 104 * 32; idx += 512) {
        int pos = idx >> 5, cp = idx & 31;
        float x0 = 0.f, x1 = 0.f;
        if (pos < 100) {
            int Y = pos / 10, X = pos - Y * 10;
            int gy = gy0 - 1 + Y, gx = gx0 - 1 + X;
            if ((unsigned)gy < HH && (unsigned)gx < WW) {
                size_t base = (size_t)(2 * cp) * (HH * WW) + gy * WW + gx;
                x0 = __ldg(xb + base);
                x1 = __ldg(xb + base + (size_t)(HH * WW));
            }
        }
        uint32_t lp, hp = pack_hi_lo(x0, x1, lp);
        uint32_t off = (uint32_t)(pos * 144 + cp * 4);
        *(uint32_t*)(smc + ARENA_F * 4 + XHI + off) = hp;
        *(uint32_t*)(smc + ARENA_F * 4 + XLO + off) = lp;
    }
    __syncthreads();

    // ============ phase 1: expand (HMMA) + depthwise 3x3, 3 chunks of 128 ============
    for (int c = 0; c < 3; ++c) {
        // W chunk -> bf16 hi/lo, layout [o(128)][k(64)+pad]
        for (int idx = tid; idx < 128 * 32; idx += 512) {
            int r = idx >> 5, cp = idx & 31;
            float2 wv = *(const float2*)(w_hidden + (size_t)(c * 128 + r) * 64 + 2 * cp);
            uint32_t lp, hp = pack_hi_lo(wv.x, wv.y, lp);
            uint32_t off = (uint32_t)(r * 144 + cp * 4);
            *(uint32_t*)(smc + ARENA_F * 4 + WHI + off) = hp;
            *(uint32_t*)(smc + ARENA_F * 4 + WLO + off) = lp;
        }
        for (int idx = tid; idx < 128 * 9; idx += 512)
            sm[OFF_DW + idx] = __ldg(w_dw + c * 128 * 9 + idx);
        __syncthreads();

        // HMMA: D[128 o][100 pos] = W @ Xt^T. warp -> (mtile = warp>>1, n-half)
        {
            const int mtile = warp >> 1, half = warp & 1;
            const uint32_t aHi = arena + WHI + (mtile * 16 + (lane & 15)) * 144
                                 + (lane >> 4) * 16;
            const uint32_t aLo = aHi + (WLO - WHI);
            uint32_t ahi[4][4], alo[4][4];
            #pragma unroll
            for (int ks = 0; ks < 4; ++ks) {
                ldsm4(ahi[ks], aHi + ks * 32);
                ldsm4(alo[ks], aLo + ks * 32);
            }
            const int nt0 = half ? 7 : 0, nt1 = half ? 13 : 7;
            for (int nt = nt0; nt < nt1; ++nt) {
                float acc[4] = {0.f, 0.f, 0.f, 0.f};
                const uint32_t bHi = arena + XHI + (nt * 8 + (lane & 7)) * 144
                                     + ((lane >> 3) & 1) * 16;
                const uint32_t bLo = bHi + (XLO - XHI);
                #pragma unroll
                for (int ks = 0; ks < 4; ++ks) {
                    uint32_t bh0, bh1, bl0, bl1;
                    ldsm2(bh0, bh1, bHi + ks * 32);
                    ldsm2(bl0, bl1, bLo + ks * 32);
                    mma16816(acc, ahi[ks], bh0, bh1);   // hi*hi
                    mma16816(acc, ahi[ks], bl0, bl1);   // hi*lo
                    mma16816(acc, alo[ks], bh0, bh1);   // lo*hi
                }
                int o = mtile * 16 + (lane >> 2);
                int p = nt * 8 + 2 * (lane & 3);
                if (p < 100) {
                    sm[OFF_HID + o * 101 + p]         = acc[0];
                    sm[OFF_HID + (o + 8) * 101 + p]   = acc[2];
                }
                if (p + 1 < 100) {
                    sm[OFF_HID + o * 101 + p + 1]       = acc[1];
                    sm[OFF_HID + (o + 8) * 101 + p + 1] = acc[3];
                }
            }
        }
        __syncthreads();

        // depthwise 3x3 (reg-blocked): thread = (channel, 2 of 8 rows)
        {
            int ch = tid & 127, rb = tid >> 7;
            const float* wd = &sm[OFF_DW + ch * 9];
            float w0 = wd[0], w1 = wd[1], w2 = wd[2], w3 = wd[3], w4 = wd[4],
                  w5 = wd[5], w6 = wd[6], w7 = wd[7], w8 = wd[8];
            const float* hb = &sm[OFF_HID + ch * 101];
            #pragma unroll
            for (int half2 = 0; half2 < 2; ++half2) {
                int rr = rb + half2 * 4;
                float r0[10], r1[10], r2[10];
                #pragma unroll
                for (int xx = 0; xx < 10; ++xx) {
                    r0[xx] = hb[rr * 10 + xx];
                    r1[xx] = hb[(rr + 1) * 10 + xx];
                    r2[xx] = hb[(rr + 2) * 10 + xx];
                }
                #pragma unroll
                for (int xx = 0; xx < 8; ++xx) {
                    float s = w0 * r0[xx];
                    s = fmaf(w1, r0[xx + 1], s); s = fmaf(w2, r0[xx + 2], s);
                    s = fmaf(w3, r1[xx], s);     s = fmaf(w4, r1[xx + 1], s);
                    s = fmaf(w5, r1[xx + 2], s); s = fmaf(w6, r2[xx], s);
                    s = fmaf(w7, r2[xx + 1], s); s = fmaf(w8, r2[xx + 2], s);
                    sm[OFF_QKV + (c * 128 + ch) * 65 + rr * 8 + xx] = s;
                }
            }
        }
        __syncthreads();
    }

    // ---------------- phase 2: RMS factors for q and k (per pixel) ----------------
    #pragma unroll
    for (int pi = 0; pi < 4; ++pi) {
        int pix = warp * 4 + pi;
        float sq = 0.f, sk = 0.f;
        #pragma unroll
        for (int r = 0; r < 4; ++r) {
            int cc = lane + r * 32;
            float qv = sm[OFF_QKV + cc * 65 + pix];
            float kv = sm[OFF_QKV + (128 + cc) * 65 + pix];
            sq = fmaf(qv, qv, sq);
            sk = fmaf(kv, kv, sk);
        }
        #pragma unroll
        for (int off = 16; off; off >>= 1) {
            sq += __shfl_xor_sync(0xffffffffu, sq, off);
            sk += __shfl_xor_sync(0xffffffffu, sk, off);
        }
        if (lane == 0) {
            sm[OFF_RQ + pix] = rsqrtf(sq * (1.f / 128.f) + EPSF);
            sm[OFF_RK + pix] = rsqrtf(sk * (1.f / 128.f) + EPSF);
        }
    }
    __syncthreads();

    // ---------------- phase 3: RMSNorm scale + 2D RoPE -----------------------------
    for (int idx = tid; idx < 64 * 64; idx += 512) {
        int m = idx >> 6, pix = idx & 63;
        int gy = gy0 + (pix >> 3), gx = gx0 + (pix & 7);
        int mm; float pos;
        if (m < 32) { mm = m;      pos = (float)gy; }
        else        { mm = m - 32; pos = (float)gx; }
        float inv = exp2f(-L2T_OVER_32 * (float)mm);
        float sn, cs;
        sincosf(pos * inv, &sn, &cs);
        int c0 = 2 * m;
        float rqp = sm[OFF_RQ + pix], rkp = sm[OFF_RK + pix];

        float q0 = sm[OFF_QKV + c0 * 65 + pix]       * rqp * __ldg(g_qnorm + c0);
        float q1 = sm[OFF_QKV + (c0 + 1) * 65 + pix] * rqp * __ldg(g_qnorm + c0 + 1);
        sm[OFF_QKV + c0 * 65 + pix]       = q0 * cs - q1 * sn;
        sm[OFF_QKV + (c0 + 1) * 65 + pix] = q1 * cs + q0 * sn;

        float k0 = sm[OFF_QKV + (128 + c0) * 65 + pix] * rkp * __ldg(g_knorm + c0);
        float k1 = sm[OFF_QKV + (129 + c0) * 65 + pix] * rkp * __ldg(g_knorm + c0 + 1);
        sm[OFF_QKV + (128 + c0) * 65 + pix] = k0 * cs - k1 * sn;
        sm[OFF_QKV + (129 + c0) * 65 + pix] = k1 * cs + k0 * sn;
    }
    __syncthreads();

    // -------- phase 4: 8x8 circular convolution per channel (direct, unrolled) -----
    {
        int cc = tid & 127;
        int A0 = (tid >> 7) * 2;
        float kreg[64];
        #pragma unroll
        for (int n = 0; n < 64; ++n) {
            int rho = n >> 3, col = n & 7;
            int srcRow = (rho + A0) & 7;
            kreg[n] = sm[OFF_QKV + (128 + cc) * 65 + srcRow * 8 + col];
        }
        float acc[2][8] = {};
        #pragma unroll
        for (int i = 0; i < 8; ++i) {
            #pragma unroll
            for (int j = 0; j < 8; ++j) {
                float qv = sm[OFF_QKV + cc * 65 + i * 8 + j];
                #pragma unroll
                for (int a2 = 0; a2 < 2; ++a2) {
                    #pragma unroll
                    for (int bb = 0; bb < 8; ++bb)
                        acc[a2][bb] = fmaf(qv, kreg[((a2 - i) & 7) * 8 + ((bb - j) & 7)],
                                           acc[a2][bb]);
                }
            }
        }
        #pragma unroll
        for (int a2 = 0; a2 < 2; ++a2)
            #pragma unroll
            for (int bb = 0; bb < 8; ++bb)
                sm[OFF_CORR + cc * 65 + (A0 + a2) * 8 + bb] = acc[a2][bb];
    }
    __syncthreads();

    // ------------- phase 5: w_proj into (dead) tile arena + corr RMS ---------------
    float* wpf = (float*)(smc + ARENA_F * 4);
    for (int idx = tid; idx < 64 * 128; idx += 512)
        wpf[idx] = __ldg(w_proj + idx);
    #pragma unroll
    for (int pi = 0; pi < 4; ++pi) {
        int pix = warp * 4 + pi;
        float sc = 0.f;
        #pragma unroll
        for (int r = 0; r < 4; ++r) {
            float cv = sm[OFF_CORR + (lane + r * 32) * 65 + pix];
            sc = fmaf(cv, cv, sc);
        }
        #pragma unroll
        for (int off = 16; off; off >>= 1)
            sc += __shfl_xor_sync(0xffffffffu, sc, off);
        if (lane == 0)
            sm[OFF_RN + pix] = rsqrtf(sc * (1.f / 128.f) + EPSF);
    }
    __syncthreads();

    // ------------- phase 6: corr <- v * g_norm * rn * corr -------------------------
    for (int idx = tid; idx < 128 * 64; idx += 512) {
        int i = idx >> 6, pix = idx & 63;
        float cv = sm[OFF_CORR + i * 65 + pix];
        float vv = sm[OFF_QKV + (256 + i) * 65 + pix];
        sm[OFF_CORR + i * 65 + pix] = vv * cv * sm[OFF_RN + pix] * __ldg(g_norm + i);
    }
    __syncthreads();

    // ------------- phase 7: 1x1 projection (64 x 128) + store ----------------------
    {
        int og = tid >> 5, pg = tid & 31;
        int o0 = og * 4, p0 = pg * 2;
        float acc[4][2] = {};
        #pragma unroll 4
        for (int kk = 0; kk < 128; ++kk) {
            float v0 = sm[OFF_CORR + kk * 65 + p0];
            float v1 = sm[OFF_CORR + kk * 65 + p0 + 1];
            #pragma unroll
            for (int j = 0; j < 4; ++j) {
                float wv = wpf[(o0 + j) * 128 + kk];
                acc[j][0] = fmaf(wv, v0, acc[j][0]);
                acc[j][1] = fmaf(wv, v1, acc[j][1]);
            }
        }
        float* ob = out + (size_t)b * 64 * HH * WW;
        #pragma unroll
        for (int j = 0; j < 4; ++j)
            #pragma unroll
            for (int e = 0; e < 2; ++e) {
                int pix = p0 + e;
                int gy = gy0 + (pix >> 3), gx = gx0 + (pix & 7);
                ob[(size_t)(o0 + j) * (HH * WW) + gy * WW + gx] = acc[j][e];
            }
    }
}

extern "C" void kernel_launch(void* const* d_in, const int* in_sizes, int n_in,
                              void* d_out, int out_size)
{
    (void)in_sizes; (void)n_in; (void)out_size;
    const float* x        = (const float*)d_in[0];
    const float* w_hidden = (const float*)d_in[1];
    const float* w_dw     = (const float*)d_in[2];
    const float* w_proj   = (const float*)d_in[3];
    const float* g_norm   = (const float*)d_in[4];
    const float* g_qnorm  = (const float*)d_in[5];
    const float* g_knorm  = (const float*)d_in[6];
    float* out = (float*)d_out;

    cudaFuncSetAttribute(fsas_fused_kernel,
                         cudaFuncAttributeMaxDynamicSharedMemorySize, SMEM_BYTES);

    dim3 grid(WW / 8, HH / 8, 4);
    fsas_fused_kernel<<<grid, 512, SMEM_BYTES>>>(
        x, w_hidden, w_dw, w_proj, g_norm, g_qnorm, g_knorm, out);
}

// round 5
// speedup vs baseline: 2.1958x; 1.3174x over previous
// FSAS_V5 fused forward — one CTA per 8x8 patch.
// Expand GEMM and projection GEMM both on mma.sync bf16 (hi/lo split ≈ fp32).
#include <cuda_runtime.h>
#include <cuda_bf16.h>
#include <cstdint>

#define HH 256
#define WW 256
#define EPSF 1e-6f
#define L2T_OVER_32 0.41524101186092030f

// ---- dynamic smem layout (float offsets) ----
#define OFF_QKV  0                 // 384 * 65 fp32               (99,840 B)
#define OFF_HID  24960             // 128 * 101 fp32 hidden chunk
#define OFF_CORR OFF_HID           // 128 * 65 overlay (phase 4+)
#define OFF_DW   37888             // 128*9 dw weights; later: sincos table(1024)+g_norm(128)
#define OFF_GN   (OFF_DW + 1024)
#define OFF_RQ   39040
#define OFF_RK   39104
#define OFF_RN   39168
#define ARENA_F  39232             // bf16 tile arena @ byte 156,928 (256-aligned)
// phase-1 arena offsets (rows strided 144 B, ldmatrix conflict-free)
#define XHI 0
#define XLO 14976
#define WHI 29952
#define WLO 48384
// proj arena offsets (rows strided 272 B = 128 bf16 + pad, 16B-aligned)
#define WPH 0
#define WPL 17408
#define CBH 34816
#define CBL 52224
#define ARENA_BYTES 69632
#define SMEM_BYTES (ARENA_F * 4 + ARENA_BYTES)   // 226,560 B

__device__ __forceinline__ uint32_t smem_u32(const void* p) {
    uint32_t a;
    asm("{ .reg .u64 t; cvta.to.shared.u64 t, %1; cvt.u32.u64 %0, t; }"
        : "=r"(a) : "l"(p));
    return a;
}
__device__ __forceinline__ void ldsm4(uint32_t* r, uint32_t addr) {
    asm volatile("ldmatrix.sync.aligned.m8n8.x4.shared.b16 {%0,%1,%2,%3}, [%4];"
                 : "=r"(r[0]), "=r"(r[1]), "=r"(r[2]), "=r"(r[3]) : "r"(addr));
}
__device__ __forceinline__ void ldsm2(uint32_t& r0, uint32_t& r1, uint32_t addr) {
    asm volatile("ldmatrix.sync.aligned.m8n8.x2.shared.b16 {%0,%1}, [%2];"
                 : "=r"(r0), "=r"(r1) : "r"(addr));
}
__device__ __forceinline__ void mma16816(float* c, const uint32_t* a,
                                         uint32_t b0, uint32_t b1) {
    asm volatile("mma.sync.aligned.m16n8k16.row.col.f32.bf16.bf16.f32 "
                 "{%0,%1,%2,%3}, {%4,%5,%6,%7}, {%8,%9}, {%0,%1,%2,%3};"
                 : "+f"(c[0]), "+f"(c[1]), "+f"(c[2]), "+f"(c[3])
                 : "r"(a[0]), "r"(a[1]), "r"(a[2]), "r"(a[3]), "r"(b0), "r"(b1));
}
__device__ __forceinline__ uint32_t pack_hi_lo(float v0, float v1, uint32_t& lo) {
    __nv_bfloat16 h0 = __float2bfloat16(v0);
    __nv_bfloat16 h1 = __float2bfloat16(v1);
    __nv_bfloat16 l0 = __float2bfloat16(v0 - __bfloat162float(h0));
    __nv_bfloat16 l1 = __float2bfloat16(v1 - __bfloat162float(h1));
    lo = ((uint32_t)__bfloat16_as_ushort(l1) << 16) | __bfloat16_as_ushort(l0);
    return ((uint32_t)__bfloat16_as_ushort(h1) << 16) | __bfloat16_as_ushort(h0);
}

__global__ __launch_bounds__(512, 1)
void fsas_fused_kernel(const float* __restrict__ x,
                       const float* __restrict__ w_hidden,
                       const float* __restrict__ w_dw,
                       const float* __restrict__ w_proj,
                       const float* __restrict__ g_norm,
                       const float* __restrict__ g_qnorm,
                       const float* __restrict__ g_knorm,
                       float* __restrict__ out)
{
    extern __shared__ float sm[];
    const int tid  = threadIdx.x;
    const int lane = tid & 31;
    const int warp = tid >> 5;
    const int px = blockIdx.x, py = blockIdx.y, b = blockIdx.z;
    const int gx0 = px * 8, gy0 = py * 8;

    char* smc = (char*)sm;
    const uint32_t sbase = smem_u32(sm);
    const uint32_t arena = sbase + ARENA_F * 4;

    // ---- phase 0: x halo -> bf16 hi/lo Xt tiles, layout [pos(104)][ch(64)+pad] ----
    const float* xb = x + (size_t)b * 64 * HH * WW;
    for (int idx = tid; idx < 104 * 32; idx += 512) {
        int pos = idx >> 5, cp = idx & 31;
        float x0 = 0.f, x1 = 0.f;
        if (pos < 100) {
            int Y = pos / 10, X = pos - Y * 10;
            int gy = gy0 - 1 + Y, gx = gx0 - 1 + X;
            if ((unsigned)gy < HH && (unsigned)gx < WW) {
                size_t base = (size_t)(2 * cp) * (HH * WW) + gy * WW + gx;
                x0 = __ldg(xb + base);
                x1 = __ldg(xb + base + (size_t)(HH * WW));
            }
        }
        uint32_t lp, hp = pack_hi_lo(x0, x1, lp);
        uint32_t off = (uint32_t)(pos * 144 + cp * 4);
        *(uint32_t*)(smc + ARENA_F * 4 + XHI + off) = hp;
        *(uint32_t*)(smc + ARENA_F * 4 + XLO + off) = lp;
    }
    __syncthreads();

    // ============ phase 1: expand (HMMA) + depthwise 3x3, 3 chunks of 128 ============
    for (int c = 0; c < 3; ++c) {
        for (int idx = tid; idx < 128 * 32; idx += 512) {
            int r = idx >> 5, cp = idx & 31;
            float2 wv = *(const float2*)(w_hidden + (size_t)(c * 128 + r) * 64 + 2 * cp);
            uint32_t lp, hp = pack_hi_lo(wv.x, wv.y, lp);
            uint32_t off = (uint32_t)(r * 144 + cp * 4);
            *(uint32_t*)(smc + ARENA_F * 4 + WHI + off) = hp;
            *(uint32_t*)(smc + ARENA_F * 4 + WLO + off) = lp;
        }
        for (int idx = tid; idx < 128 * 9; idx += 512)
            sm[OFF_DW + idx] = __ldg(w_dw + c * 128 * 9 + idx);
        __syncthreads();

        // HMMA: D[128 o][100 pos] = W @ Xt^T
        {
            const int mtile = warp >> 1, half = warp & 1;
            const uint32_t aHi = arena + WHI + (mtile * 16 + (lane & 15)) * 144
                                 + (lane >> 4) * 16;
            const uint32_t aLo = aHi + (WLO - WHI);
            uint32_t ahi[4][4], alo[4][4];
            #pragma unroll
            for (int ks = 0; ks < 4; ++ks) {
                ldsm4(ahi[ks], aHi + ks * 32);
                ldsm4(alo[ks], aLo + ks * 32);
            }
            const int nt0 = half ? 7 : 0, nt1 = half ? 13 : 7;
            for (int nt = nt0; nt < nt1; ++nt) {
                float acc[4] = {0.f, 0.f, 0.f, 0.f};
                const uint32_t bHi = arena + XHI + (nt * 8 + (lane & 7)) * 144
                                     + ((lane >> 3) & 1) * 16;
                const uint32_t bLo = bHi + (XLO - XHI);
                #pragma unroll
                for (int ks = 0; ks < 4; ++ks) {
                    uint32_t bh0, bh1, bl0, bl1;
                    ldsm2(bh0, bh1, bHi + ks * 32);
                    ldsm2(bl0, bl1, bLo + ks * 32);
                    mma16816(acc, ahi[ks], bh0, bh1);
                    mma16816(acc, ahi[ks], bl0, bl1);
                    mma16816(acc, alo[ks], bh0, bh1);
                }
                int o = mtile * 16 + (lane >> 2);
                int p = nt * 8 + 2 * (lane & 3);
                if (p < 100) {
                    sm[OFF_HID + o * 101 + p]       = acc[0];
                    sm[OFF_HID + (o + 8) * 101 + p] = acc[2];
                }
                if (p + 1 < 100) {
                    sm[OFF_HID + o * 101 + p + 1]       = acc[1];
                    sm[OFF_HID + (o + 8) * 101 + p + 1] = acc[3];
                }
            }
        }
        __syncthreads();

        // depthwise 3x3 (reg-blocked)
        {
            int ch = tid & 127, rb = tid >> 7;
            const float* wd = &sm[OFF_DW + ch * 9];
            float w0 = wd[0], w1 = wd[1], w2 = wd[2], w3 = wd[3], w4 = wd[4],
                  w5 = wd[5], w6 = wd[6], w7 = wd[7], w8 = wd[8];
            const float* hb = &sm[OFF_HID + ch * 101];
            #pragma unroll
            for (int half2 = 0; half2 < 2; ++half2) {
                int rr = rb + half2 * 4;
                float r0[10], r1[10], r2[10];
                #pragma unroll
                for (int xx = 0; xx < 10; ++xx) {
                    r0[xx] = hb[rr * 10 + xx];
                    r1[xx] = hb[(rr + 1) * 10 + xx];
                    r2[xx] = hb[(rr + 2) * 10 + xx];
                }
                #pragma unroll
                for (int xx = 0; xx < 8; ++xx) {
                    float s = w0 * r0[xx];
                    s = fmaf(w1, r0[xx + 1], s); s = fmaf(w2, r0[xx + 2], s);
                    s = fmaf(w3, r1[xx], s);     s = fmaf(w4, r1[xx + 1], s);
                    s = fmaf(w5, r1[xx + 2], s); s = fmaf(w6, r2[xx], s);
                    s = fmaf(w7, r2[xx + 1], s); s = fmaf(w8, r2[xx + 2], s);
                    sm[OFF_QKV + (c * 128 + ch) * 65 + rr * 8 + xx] = s;
                }
            }
        }
        __syncthreads();
    }

    // ---- phase 1.5: prefetch w_proj into regs; g_norm into smem ----
    float2 wreg[8];
    #pragma unroll
    for (int t = 0; t < 8; ++t)
        wreg[t] = __ldg((const float2*)w_proj + (tid + t * 512));
    if (tid < 128) sm[OFF_GN + tid] = __ldg(g_norm + tid);

    // ---- phase 2a: sincos table (flag, m, d): cos @ OFF_DW, sin @ OFF_DW+512 ----
    {
        int flag = tid >> 8, mm = (tid >> 3) & 31, d = tid & 7;
        float pos = (float)((flag ? gx0 : gy0) + d);
        float inv = exp2f(-L2T_OVER_32 * (float)mm);
        float sn, cs;
        sincosf(pos * inv, &sn, &cs);
        sm[OFF_DW + flag * 256 + mm * 8 + d]       = cs;
        sm[OFF_DW + 512 + flag * 256 + mm * 8 + d] = sn;
    }

    // ---- phase 2b: RMS factors for q and k (per pixel) ----
    #pragma unroll
    for (int pi = 0; pi < 4; ++pi) {
        int pix = warp * 4 + pi;
        float sq = 0.f, sk = 0.f;
        #pragma unroll
        for (int r = 0; r < 4; ++r) {
            int cc = lane + r * 32;
            float qv = sm[OFF_QKV + cc * 65 + pix];
            float kv = sm[OFF_QKV + (128 + cc) * 65 + pix];
            sq = fmaf(qv, qv, sq);
            sk = fmaf(kv, kv, sk);
        }
        #pragma unroll
        for (int off = 16; off; off >>= 1) {
            sq += __shfl_xor_sync(0xffffffffu, sq, off);
            sk += __shfl_xor_sync(0xffffffffu, sk, off);
        }
        if (lane == 0) {
            sm[OFF_RQ + pix] = rsqrtf(sq * (1.f / 128.f) + EPSF);
            sm[OFF_RK + pix] = rsqrtf(sk * (1.f / 128.f) + EPSF);
        }
    }
    __syncthreads();

    // ---- phase 3: RMSNorm scale + 2D RoPE (table-driven) ----
    for (int idx = tid; idx < 64 * 64; idx += 512) {
        int m = idx >> 6, pix = idx & 63;
        int flag = (m >> 5), mm = m & 31;
        int d = flag ? (pix & 7) : (pix >> 3);
        float cs = sm[OFF_DW + flag * 256 + mm * 8 + d];
        float sn = sm[OFF_DW + 512 + flag * 256 + mm * 8 + d];
        int c0 = 2 * m;
        float rqp = sm[OFF_RQ + pix], rkp = sm[OFF_RK + pix];

        float q0 = sm[OFF_QKV + c0 * 65 + pix]       * rqp * __ldg(g_qnorm + c0);
        float q1 = sm[OFF_QKV + (c0 + 1) * 65 + pix] * rqp * __ldg(g_qnorm + c0 + 1);
        sm[OFF_QKV + c0 * 65 + pix]       = q0 * cs - q1 * sn;
        sm[OFF_QKV + (c0 + 1) * 65 + pix] = q1 * cs + q0 * sn;

        float k0 = sm[OFF_QKV + (128 + c0) * 65 + pix] * rkp * __ldg(g_knorm + c0);
        float k1 = sm[OFF_QKV + (129 + c0) * 65 + pix] * rkp * __ldg(g_knorm + c0 + 1);
        sm[OFF_QKV + (128 + c0) * 65 + pix] = k0 * cs - k1 * sn;
        sm[OFF_QKV + (129 + c0) * 65 + pix] = k1 * cs + k0 * sn;
    }

    // ---- phase 3.5: w_proj -> bf16 hi/lo tiles [o(64)][k(128)] stride 272 ----
    #pragma unroll
    for (int t = 0; t < 8; ++t) {
        int idx = tid + t * 512;
        int o = idx >> 6, kp = idx & 63;
        uint32_t lp, hp = pack_hi_lo(wreg[t].x, wreg[t].y, lp);
        *(uint32_t*)(smc + ARENA_F * 4 + WPH + o * 272 + kp * 4) = hp;
        *(uint32_t*)(smc + ARENA_F * 4 + WPL + o * 272 + kp * 4) = lp;
    }
    __syncthreads();

    // ---- phase 4: 8x8 circular convolution per channel (direct, unrolled) ----
    {
        int cc = tid & 127;
        int A0 = (tid >> 7) * 2;
        float kreg[64];
        #pragma unroll
        for (int n = 0; n < 64; ++n) {
            int rho = n >> 3, col = n & 7;
            int srcRow = (rho + A0) & 7;
            kreg[n] = sm[OFF_QKV + (128 + cc) * 65 + srcRow * 8 + col];
        }
        float acc[2][8] = {};
        #pragma unroll
        for (int i = 0; i < 8; ++i) {
            #pragma unroll
            for (int j = 0; j < 8; ++j) {
                float qv = sm[OFF_QKV + cc * 65 + i * 8 + j];
                #pragma unroll
                for (int a2 = 0; a2 < 2; ++a2) {
                    #pragma unroll
                    for (int bb = 0; bb < 8; ++bb)
                        acc[a2][bb] = fmaf(qv, kreg[((a2 - i) & 7) * 8 + ((bb - j) & 7)],
                                           acc[a2][bb]);
                }
            }
        }
        #pragma unroll
        for (int a2 = 0; a2 < 2; ++a2)
            #pragma unroll
            for (int bb = 0; bb < 8; ++bb)
                sm[OFF_CORR + cc * 65 + (A0 + a2) * 8 + bb] = acc[a2][bb];
    }
    __syncthreads();

    // ---- phase 5: corr RMS factor per pixel ----
    #pragma unroll
    for (int pi = 0; pi < 4; ++pi) {
        int pix = warp * 4 + pi;
        float sc = 0.f;
        #pragma unroll
        for (int r = 0; r < 4; ++r) {
            float cv = sm[OFF_CORR + (lane + r * 32) * 65 + pix];
            sc = fmaf(cv, cv, sc);
        }
        #pragma unroll
        for (int off = 16; off; off >>= 1)
            sc += __shfl_xor_sync(0xffffffffu, sc, off);
        if (lane == 0)
            sm[OFF_RN + pix] = rsqrtf(sc * (1.f / 128.f) + EPSF);
    }
    __syncthreads();

    // ---- phase 6: (v * g_norm * rn * corr) -> bf16 hi/lo B tiles [pix][k] ----
    for (int idx = tid; idx < 64 * 64; idx += 512) {
        int pix = idx >> 6, kp = idx & 63;
        int k0 = 2 * kp;
        float rnp = sm[OFF_RN + pix];
        float c0v = sm[OFF_CORR + k0 * 65 + pix];
        float c1v = sm[OFF_CORR + (k0 + 1) * 65 + pix];
        float v0  = sm[OFF_QKV + (256 + k0) * 65 + pix];
        float v1  = sm[OFF_QKV + (257 + k0) * 65 + pix];
        float g0  = sm[OFF_GN + k0], g1 = sm[OFF_GN + k0 + 1];
        float w0 = v0 * c0v * rnp * g0;
        float w1 = v1 * c1v * rnp * g1;
        uint32_t lp, hp = pack_hi_lo(w0, w1, lp);
        *(uint32_t*)(smc + ARENA_F * 4 + CBH + pix * 272 + kp * 4) = hp;
        *(uint32_t*)(smc + ARENA_F * 4 + CBL + pix * 272 + kp * 4) = lp;
    }
    __syncthreads();

    // ---- phase 7: projection HMMA: out[64 o][64 pix] = Wp @ corrB^T ----
    {
        const int mtile = warp & 3;
        const int ntbase = (warp >> 2) * 2;
        const uint32_t aH = arena + WPH + (mtile * 16 + (lane & 15)) * 272
                            + (lane >> 4) * 16;
        const uint32_t aL = aH + (WPL - WPH);
        uint32_t bAddr0 = arena + CBH + ((ntbase + 0) * 8 + (lane & 7)) * 272
                          + ((lane >> 3) & 1) * 16;
        uint32_t bAddr1 = bAddr0 + 8 * 272;
        float acc[2][4] = {};
        #pragma unroll
        for (int ks = 0; ks < 8; ++ks) {
            uint32_t ahi[4], alo[4];
            ldsm4(ahi, aH + ks * 32);
            ldsm4(alo, aL + ks * 32);
            #pragma unroll
            for (int t = 0; t < 2; ++t) {
                uint32_t bA = (t ? bAddr1 : bAddr0) + ks * 32;
                uint32_t bh0, bh1, bl0, bl1;
                ldsm2(bh0, bh1, bA);
                ldsm2(bl0, bl1, bA + (CBL - CBH));
                mma16816(acc[t], ahi, bh0, bh1);
                mma16816(acc[t], ahi, bl0, bl1);
                mma16816(acc[t], alo, bh0, bh1);
            }
        }
        float* ob = out + (size_t)b * 64 * HH * WW;
        int o = mtile * 16 + (lane >> 2);
        int gxp = gx0 + 2 * (lane & 3);
        #pragma unroll
        for (int t = 0; t < 2; ++t) {
            int gy = gy0 + ntbase + t;
            float2 r0 = make_float2(acc[t][0], acc[t][1]);
            float2 r1 = make_float2(acc[t][2], acc[t][3]);
            *(float2*)(ob + (size_t)o * (HH * WW) + gy * WW + gxp)       = r0;
            *(float2*)(ob + (size_t)(o + 8) * (HH * WW) + gy * WW + gxp) = r1;
        }
    }
}

extern "C" void kernel_launch(void* const* d_in, const int* in_sizes, int n_in,
                              void* d_out, int out_size)
{
    (void)in_sizes; (void)n_in; (void)out_size;
    const float* x        = (const float*)d_in[0];
    const float* w_hidden = (const float*)d_in[1];
    const float* w_dw     = (const float*)d_in[2];
    const float* w_proj   = (const float*)d_in[3];
    const float* g_norm   = (const float*)d_in[4];
    const float* g_qnorm  = (const float*)d_in[5];
    const float* g_knorm  = (const float*)d_in[6];
    float* out = (float*)d_out;

    cudaFuncSetAttribute(fsas_fused_kernel,
                         cudaFuncAttributeMaxDynamicSharedMemorySize, SMEM_BYTES);

    dim3 grid(WW / 8, HH / 8, 4);
    fsas_fused_kernel<<<grid, 512, SMEM_BYTES>>>(
        x, w_hidden, w_dw, w_proj, g_norm, g_qnorm, g_knorm, out);
}